// round 6
// baseline (speedup 1.0000x reference)
#include <cuda_runtime.h>

#define NB 8
#define NN 512
#define DD 256
#define DH 64
#define OUT_ELEMS (NB*NN*DH)            // 262144
#define E4        16777216u             // e element count / 4
#define E4_K1     12582912u             // 3/4 of e copied in kernel 1

#define QKV_BLOCKS 192                  // 3 mats * 64 row-tiles
#define COPY1 1536u                     // copies E4_K1: 32 float4/thread exact
#define ATT_BLOCKS 256                  // 8 batches * 32 i-tiles of 16
#define COPY2 512u                      // copies remaining 1/4: 32 f4/thread exact

__device__ float g_Q[NB*NN*DH];
__device__ float g_K[NB*NN*DH];
__device__ float g_V[NB*NN*DH];

// ---------------------------------------------------------------------------
// Kernel 1: QKV projection (tiled SGEMM) + 3/4 of the e copy
// ---------------------------------------------------------------------------
__global__ void __launch_bounds__(256) k1_qkv_copy(
    const float* __restrict__ x, const int* __restrict__ mask,
    const float* __restrict__ Wq, const float* __restrict__ bq,
    const float* __restrict__ Wk, const float* __restrict__ bk,
    const float* __restrict__ Wv, const float* __restrict__ bv,
    const float4* __restrict__ e4, float4* __restrict__ eo4)
{
    if (blockIdx.x >= QKV_BLOCKS) {
        // streaming copy, MLP=4: 32 float4 per thread exactly.
        unsigned cid = blockIdx.x - QKV_BLOCKS;
        unsigned i = cid * 256u + threadIdx.x;
        const unsigned S = COPY1 * 256u;          // 393216
        #pragma unroll 1
        for (int it = 0; it < 8; it++) {
            float4 a = __ldcs(e4 + i);
            float4 b = __ldcs(e4 + i + S);
            float4 c = __ldcs(e4 + i + 2u*S);
            float4 d = __ldcs(e4 + i + 3u*S);
            __stcs(eo4 + i,        a);
            __stcs(eo4 + i + S,    b);
            __stcs(eo4 + i + 2u*S, c);
            __stcs(eo4 + i + 3u*S, d);
            i += 4u*S;
        }
        return;
    }

    __shared__ float Xs[64 * 65];
    __shared__ float Ws[64 * 64];

    int which  = blockIdx.x >> 6;         // 0=Q, 1=K, 2=V
    int rowblk = blockIdx.x & 63;
    const float* W    = (which == 0) ? Wq : (which == 1) ? Wk : Wv;
    const float* bias = (which == 0) ? bq : (which == 1) ? bk : bv;
    float* outw       = (which == 0) ? g_Q : (which == 1) ? g_K : g_V;

    int t  = threadIdx.x;
    int tx = t & 15;
    int ty = t >> 4;
    int row0 = rowblk * 64;

    float acc[4][4];
    #pragma unroll
    for (int i = 0; i < 4; i++)
        #pragma unroll
        for (int j = 0; j < 4; j++) acc[i][j] = 0.f;

    for (int kt = 0; kt < 4; kt++) {
        int k0 = kt * 64;
        __syncthreads();
        #pragma unroll
        for (int idx = t; idx < 4096; idx += 256) {
            int r  = idx >> 6;
            int kk = idx & 63;
            Xs[r * 65 + kk] = x[(row0 + r) * DD + k0 + kk];
            Ws[idx]         = W[k0 * DH + idx];
        }
        __syncthreads();

        const float4* Ws4 = (const float4*)Ws;
        #pragma unroll 8
        for (int kk = 0; kk < 64; kk++) {
            float4 bv4 = Ws4[kk * 16 + tx];
            #pragma unroll
            for (int i = 0; i < 4; i++) {
                float a = Xs[(ty * 4 + i) * 65 + kk];
                acc[i][0] += a * bv4.x;
                acc[i][1] += a * bv4.y;
                acc[i][2] += a * bv4.z;
                acc[i][3] += a * bv4.w;
            }
        }
    }

    #pragma unroll
    for (int i = 0; i < 4; i++) {
        int r = row0 + ty * 4 + i;
        float m = (float)mask[r];
        float4 o;
        o.x = (acc[i][0] + bias[tx * 4 + 0]) * m;
        o.y = (acc[i][1] + bias[tx * 4 + 1]) * m;
        o.z = (acc[i][2] + bias[tx * 4 + 2]) * m;
        o.w = (acc[i][3] + bias[tx * 4 + 3]) * m;
        *(float4*)(outw + r * DH + tx * 4) = o;
    }
}

// ---------------------------------------------------------------------------
// Kernel 2: flash-style masked attention (16 q/block, round-2 proven body)
//           + last 1/4 of the e copy
// ---------------------------------------------------------------------------
__global__ void __launch_bounds__(256) k2_attn_copy(
    const int* __restrict__ mask, float* __restrict__ outp,
    const float4* __restrict__ e4, float4* __restrict__ eo4)
{
    if (blockIdx.x >= ATT_BLOCKS) {
        unsigned cid = blockIdx.x - ATT_BLOCKS;
        unsigned i = E4_K1 + cid * 256u + threadIdx.x;
        const unsigned S = COPY2 * 256u;          // 131072
        #pragma unroll 1
        for (int it = 0; it < 8; it++) {
            float4 a = __ldcs(e4 + i);
            float4 b = __ldcs(e4 + i + S);
            float4 c = __ldcs(e4 + i + 2u*S);
            float4 d = __ldcs(e4 + i + 3u*S);
            __stcs(eo4 + i,        a);
            __stcs(eo4 + i + S,    b);
            __stcs(eo4 + i + 2u*S, c);
            __stcs(eo4 + i + 3u*S, d);
            i += 4u*S;
        }
        return;
    }

    __shared__ float Qs[16 * 64];
    __shared__ float Ks[64 * 68];   // padded: conflict-free per-j access
    __shared__ float Vs[64 * 64];
    __shared__ float Ss[16 * 64];
    __shared__ int   mj_s[64];
    __shared__ int   mi_s[16];

    int blk = blockIdx.x;
    int b   = blk >> 5;
    int i0  = (blk & 31) << 4;
    int t   = threadIdx.x;

    const float* Qg = g_Q + (b * NN + i0) * DH;
    #pragma unroll
    for (int idx = t; idx < 1024; idx += 256) Qs[idx] = Qg[idx];
    if (t < 16) mi_s[t] = mask[b * NN + i0 + t];

    int ig  = t >> 4;   // phase-2 / accumulate mapping: query row
    int l16 = t & 15;   // 4 dh columns each
    int jl  = t & 63;   // phase-1 mapping: key index in chunk
    int ih  = t >> 6;   // phase-1: 4 query rows each

    const float NEGINF = __int_as_float(0xff800000);
    float m_i = NEGINF, l_i = 0.f;
    float4 acc = make_float4(0.f, 0.f, 0.f, 0.f);

    const float4* Qs4 = (const float4*)Qs;
    const float4* Ks4 = (const float4*)Ks;
    const float4* Vs4 = (const float4*)Vs;
    float4* Ss4 = (float4*)Ss;

    for (int c = 0; c < 8; c++) {
        int j0 = c * 64;
        __syncthreads();
        const float* Kg = g_K + (b * NN + j0) * DH;
        const float* Vg = g_V + (b * NN + j0) * DH;
        #pragma unroll
        for (int idx = t; idx < 4096; idx += 256) {
            Ks[(idx >> 6) * 68 + (idx & 63)] = Kg[idx];
            Vs[idx] = Vg[idx];
        }
        if (t < 64) mj_s[t] = mask[b * NN + j0 + t];
        __syncthreads();

        // ---- phase 1: scores S[i][j], conflict-free K reads ----
        float s0 = 0.f, s1 = 0.f, s2 = 0.f, s3 = 0.f;
        #pragma unroll
        for (int k4 = 0; k4 < 16; k4++) {
            float4 kv = Ks4[jl * 17 + k4];
            float4 q;
            q = Qs4[(ih * 4 + 0) * 16 + k4];
            s0 += q.x * kv.x + q.y * kv.y + q.z * kv.z + q.w * kv.w;
            q = Qs4[(ih * 4 + 1) * 16 + k4];
            s1 += q.x * kv.x + q.y * kv.y + q.z * kv.z + q.w * kv.w;
            q = Qs4[(ih * 4 + 2) * 16 + k4];
            s2 += q.x * kv.x + q.y * kv.y + q.z * kv.z + q.w * kv.w;
            q = Qs4[(ih * 4 + 3) * 16 + k4];
            s3 += q.x * kv.x + q.y * kv.y + q.z * kv.z + q.w * kv.w;
        }
        bool mj = (mj_s[jl] != 0);
        Ss[(ih * 4 + 0) * 64 + jl] = mj ? s0 * 0.125f : -1.0e9f;
        Ss[(ih * 4 + 1) * 64 + jl] = mj ? s1 * 0.125f : -1.0e9f;
        Ss[(ih * 4 + 2) * 64 + jl] = mj ? s2 * 0.125f : -1.0e9f;
        Ss[(ih * 4 + 3) * 64 + jl] = mj ? s3 * 0.125f : -1.0e9f;
        __syncthreads();

        // ---- phase 2: online softmax per query row (16-lane groups) ----
        float4 sv = Ss4[ig * 16 + l16];
        float cm = fmaxf(fmaxf(sv.x, sv.y), fmaxf(sv.z, sv.w));
        #pragma unroll
        for (int off = 8; off; off >>= 1)
            cm = fmaxf(cm, __shfl_xor_sync(0xffffffffu, cm, off));
        float m_new = fmaxf(m_i, cm);
        float coef  = __expf(m_i - m_new);
        float4 p;
        p.x = __expf(sv.x - m_new);
        p.y = __expf(sv.y - m_new);
        p.z = __expf(sv.z - m_new);
        p.w = __expf(sv.w - m_new);
        float ps = p.x + p.y + p.z + p.w;
        #pragma unroll
        for (int off = 8; off; off >>= 1)
            ps += __shfl_xor_sync(0xffffffffu, ps, off);
        l_i = l_i * coef + ps;
        m_i = m_new;
        acc.x *= coef; acc.y *= coef; acc.z *= coef; acc.w *= coef;
        Ss4[ig * 16 + l16] = p;
        __syncwarp();

        // ---- accumulate O += P @ V ----
        #pragma unroll 8
        for (int j = 0; j < 64; j++) {
            float pv = Ss[ig * 64 + j];
            float4 v = Vs4[j * 16 + l16];
            acc.x += pv * v.x;
            acc.y += pv * v.y;
            acc.z += pv * v.z;
            acc.w += pv * v.w;
        }
    }

    float inv = mi_s[ig] ? (1.f / l_i) : 0.f;   // out *= x_mask
    float4 o = make_float4(acc.x * inv, acc.y * inv, acc.z * inv, acc.w * inv);
    *(float4*)(outp + (b * NN + i0 + ig) * DH + l16 * 4) = o;
}

// ---------------------------------------------------------------------------
extern "C" void kernel_launch(void* const* d_in, const int* in_sizes, int n_in,
                              void* d_out, int out_size)
{
    const float* x    = (const float*)d_in[0];
    const float* e    = (const float*)d_in[1];
    const int*   mask = (const int*)  d_in[2];
    const float* Wq   = (const float*)d_in[3];
    const float* bq   = (const float*)d_in[4];
    const float* Wk   = (const float*)d_in[5];
    const float* bk   = (const float*)d_in[6];
    const float* Wv   = (const float*)d_in[7];
    const float* bv   = (const float*)d_in[8];

    float* outp = (float*)d_out;
    const float4* e4 = (const float4*)e;
    float4* eo4 = (float4*)(outp + OUT_ELEMS);

    k1_qkv_copy<<<QKV_BLOCKS + COPY1, 256>>>(x, mask, Wq, bq, Wk, bk, Wv, bv, e4, eo4);
    k2_attn_copy<<<ATT_BLOCKS + COPY2, 256>>>(mask, outp, e4, eo4);
}

// round 7
// speedup vs baseline: 1.2907x; 1.2907x over previous
#include <cuda_runtime.h>

#define NB 8
#define NN 512
#define DD 256
#define DH 64
#define OUT_ELEMS (NB*NN*DH)            // 262144
#define E4        16777216u             // e element count / 4

#define NBLK_QKV 192
#define NBLK_ATT 256
#define NBLK_CPY 1536
#define GRID     (NBLK_QKV + NBLK_ATT + NBLK_CPY)   // 1984
#define CPY_LANES ((NBLK_QKV + NBLK_CPY) * 256u)    // 442368 threads copy

__device__ float g_Q[NB*NN*DH];
__device__ float g_K[NB*NN*DH];
__device__ float g_V[NB*NN*DH];
__device__ unsigned g_qkv_done = 0;
__device__ unsigned g_att_done = 0;

__device__ __forceinline__ void do_copy(unsigned lane, unsigned t,
                                        const float4* __restrict__ e4,
                                        float4* __restrict__ eo4)
{
    const unsigned L = CPY_LANES;
    unsigned g = lane * 256u + t;
    #pragma unroll 1
    for (unsigned base = g; base < E4; base += 4u * L) {
        unsigned i1 = base + L, i2 = base + 2u*L, i3 = base + 3u*L;
        bool h1 = i1 < E4, h2 = i2 < E4, h3 = i3 < E4;
        float4 a = __ldcs(e4 + base);
        float4 b, c, d;
        if (h1) b = __ldcs(e4 + i1);
        if (h2) c = __ldcs(e4 + i2);
        if (h3) d = __ldcs(e4 + i3);
        __stcs(eo4 + base, a);
        if (h1) __stcs(eo4 + i1, b);
        if (h2) __stcs(eo4 + i2, c);
        if (h3) __stcs(eo4 + i3, d);
    }
}

__global__ void __launch_bounds__(256) fused_kernel(
    const float* __restrict__ x, const int* __restrict__ mask,
    const float* __restrict__ Wq, const float* __restrict__ bq,
    const float* __restrict__ Wk, const float* __restrict__ bk,
    const float* __restrict__ Wv, const float* __restrict__ bv,
    const float4* __restrict__ e4, float4* __restrict__ eo4,
    float* __restrict__ outp)
{
    __shared__ __align__(16) char sm_raw[42368];
    int t = threadIdx.x;
    unsigned bid = blockIdx.x;

    if (bid < NBLK_QKV) {
        // =================== QKV GEMM role ===================
        float* Xs = (float*)sm_raw;          // 64*65
        float* Ws = Xs + 64*65;              // 64*64

        int which  = bid / 64;               // 0=Q, 1=K, 2=V
        int rowblk = bid % 64;
        const float* W    = (which == 0) ? Wq : (which == 1) ? Wk : Wv;
        const float* bias = (which == 0) ? bq : (which == 1) ? bk : bv;
        float* outw       = (which == 0) ? g_Q : (which == 1) ? g_K : g_V;

        int tx = t & 15;
        int ty = t >> 4;
        int row0 = rowblk * 64;

        float acc[4][4];
        #pragma unroll
        for (int i = 0; i < 4; i++)
            #pragma unroll
            for (int j = 0; j < 4; j++) acc[i][j] = 0.f;

        for (int kt = 0; kt < 4; kt++) {
            int k0 = kt * 64;
            __syncthreads();
            #pragma unroll
            for (int idx = t; idx < 4096; idx += 256) {
                int r  = idx >> 6;
                int kk = idx & 63;
                Xs[r * 65 + kk] = x[(row0 + r) * DD + k0 + kk];
                Ws[idx]         = W[k0 * DH + idx];
            }
            __syncthreads();

            const float4* Ws4 = (const float4*)Ws;
            #pragma unroll 8
            for (int kk = 0; kk < 64; kk++) {
                float4 bv4 = Ws4[kk * 16 + tx];
                #pragma unroll
                for (int i = 0; i < 4; i++) {
                    float a = Xs[(ty * 4 + i) * 65 + kk];
                    acc[i][0] += a * bv4.x;
                    acc[i][1] += a * bv4.y;
                    acc[i][2] += a * bv4.z;
                    acc[i][3] += a * bv4.w;
                }
            }
        }

        #pragma unroll
        for (int i = 0; i < 4; i++) {
            int r = row0 + ty * 4 + i;
            float m = (float)mask[r];
            float4 o;
            o.x = (acc[i][0] + bias[tx * 4 + 0]) * m;
            o.y = (acc[i][1] + bias[tx * 4 + 1]) * m;
            o.z = (acc[i][2] + bias[tx * 4 + 2]) * m;
            o.w = (acc[i][3] + bias[tx * 4 + 3]) * m;
            *(float4*)(outw + r * DH + tx * 4) = o;
        }

        // publish QKV, then join the copy crew
        __threadfence();
        __syncthreads();
        if (t == 0) atomicAdd(&g_qkv_done, 1u);

        do_copy(bid, (unsigned)t, e4, eo4);
        return;
    }

    if (bid >= NBLK_QKV + NBLK_ATT) {
        // =================== pure copy role ===================
        do_copy(bid - NBLK_ATT, (unsigned)t, e4, eo4);
        return;
    }

    // =================== attention role ===================
    // wait for all QKV blocks (they hold the lowest bids -> always resident first)
    if (t == 0) {
        while (atomicAdd(&g_qkv_done, 0u) < (unsigned)NBLK_QKV)
            __nanosleep(64);
    }
    __syncthreads();
    __threadfence();

    float* Qs   = (float*)sm_raw;        // 16*64
    float* Ks   = Qs + 1024;             // 64*68 padded
    float* Vs   = Ks + 64*68;            // 64*64
    float* Ss   = Vs + 4096;             // 16*64
    int*   mj_s = (int*)(Ss + 1024);     // 64
    int*   mi_s = mj_s + 64;             // 16

    int blk = bid - NBLK_QKV;
    int b   = blk >> 5;
    int i0  = (blk & 31) << 4;

    const float* Qg = g_Q + (b * NN + i0) * DH;
    #pragma unroll
    for (int idx = t; idx < 1024; idx += 256) Qs[idx] = Qg[idx];
    if (t < 16) mi_s[t] = mask[b * NN + i0 + t];

    int ig  = t >> 4;
    int l16 = t & 15;
    int jl  = t & 63;
    int ih  = t >> 6;

    const float NEGINF = __int_as_float(0xff800000);
    float m_i = NEGINF, l_i = 0.f;
    float4 acc = make_float4(0.f, 0.f, 0.f, 0.f);

    const float4* Qs4 = (const float4*)Qs;
    const float4* Ks4 = (const float4*)Ks;
    const float4* Vs4 = (const float4*)Vs;
    float4* Ss4 = (float4*)Ss;

    for (int c = 0; c < 8; c++) {
        int j0 = c * 64;
        __syncthreads();
        const float* Kg = g_K + (b * NN + j0) * DH;
        const float* Vg = g_V + (b * NN + j0) * DH;
        #pragma unroll
        for (int idx = t; idx < 4096; idx += 256) {
            Ks[(idx >> 6) * 68 + (idx & 63)] = Kg[idx];
            Vs[idx] = Vg[idx];
        }
        if (t < 64) mj_s[t] = mask[b * NN + j0 + t];
        __syncthreads();

        float s0 = 0.f, s1 = 0.f, s2 = 0.f, s3 = 0.f;
        #pragma unroll
        for (int k4 = 0; k4 < 16; k4++) {
            float4 kv = Ks4[jl * 17 + k4];
            float4 q;
            q = Qs4[(ih * 4 + 0) * 16 + k4];
            s0 += q.x * kv.x + q.y * kv.y + q.z * kv.z + q.w * kv.w;
            q = Qs4[(ih * 4 + 1) * 16 + k4];
            s1 += q.x * kv.x + q.y * kv.y + q.z * kv.z + q.w * kv.w;
            q = Qs4[(ih * 4 + 2) * 16 + k4];
            s2 += q.x * kv.x + q.y * kv.y + q.z * kv.z + q.w * kv.w;
            q = Qs4[(ih * 4 + 3) * 16 + k4];
            s3 += q.x * kv.x + q.y * kv.y + q.z * kv.z + q.w * kv.w;
        }
        bool mj = (mj_s[jl] != 0);
        Ss[(ih * 4 + 0) * 64 + jl] = mj ? s0 * 0.125f : -1.0e9f;
        Ss[(ih * 4 + 1) * 64 + jl] = mj ? s1 * 0.125f : -1.0e9f;
        Ss[(ih * 4 + 2) * 64 + jl] = mj ? s2 * 0.125f : -1.0e9f;
        Ss[(ih * 4 + 3) * 64 + jl] = mj ? s3 * 0.125f : -1.0e9f;
        __syncthreads();

        float4 sv = Ss4[ig * 16 + l16];
        float cm = fmaxf(fmaxf(sv.x, sv.y), fmaxf(sv.z, sv.w));
        #pragma unroll
        for (int off = 8; off; off >>= 1)
            cm = fmaxf(cm, __shfl_xor_sync(0xffffffffu, cm, off));
        float m_new = fmaxf(m_i, cm);
        float coef  = __expf(m_i - m_new);
        float4 p;
        p.x = __expf(sv.x - m_new);
        p.y = __expf(sv.y - m_new);
        p.z = __expf(sv.z - m_new);
        p.w = __expf(sv.w - m_new);
        float ps = p.x + p.y + p.z + p.w;
        #pragma unroll
        for (int off = 8; off; off >>= 1)
            ps += __shfl_xor_sync(0xffffffffu, ps, off);
        l_i = l_i * coef + ps;
        m_i = m_new;
        acc.x *= coef; acc.y *= coef; acc.z *= coef; acc.w *= coef;
        Ss4[ig * 16 + l16] = p;
        __syncwarp();

        #pragma unroll 8
        for (int j = 0; j < 64; j++) {
            float pv = Ss[ig * 64 + j];
            float4 v = Vs4[j * 16 + l16];
            acc.x += pv * v.x;
            acc.y += pv * v.y;
            acc.z += pv * v.z;
            acc.w += pv * v.w;
        }
    }

    float inv = mi_s[ig] ? (1.f / l_i) : 0.f;
    float4 o = make_float4(acc.x * inv, acc.y * inv, acc.z * inv, acc.w * inv);
    *(float4*)(outp + (b * NN + i0 + ig) * DH + l16 * 4) = o;

    // replay-safe counter reset: the 256th attention block resets both counters.
    // All 256 att blocks have necessarily passed the spin before this fires.
    __syncthreads();
    if (t == 0) {
        unsigned r = atomicAdd(&g_att_done, 1u);
        if (r == (unsigned)(NBLK_ATT - 1)) {
            atomicExch(&g_qkv_done, 0u);
            atomicExch(&g_att_done, 0u);
        }
    }
}

// ---------------------------------------------------------------------------
extern "C" void kernel_launch(void* const* d_in, const int* in_sizes, int n_in,
                              void* d_out, int out_size)
{
    const float* x    = (const float*)d_in[0];
    const float* e    = (const float*)d_in[1];
    const int*   mask = (const int*)  d_in[2];
    const float* Wq   = (const float*)d_in[3];
    const float* bq   = (const float*)d_in[4];
    const float* Wk   = (const float*)d_in[5];
    const float* bk   = (const float*)d_in[6];
    const float* Wv   = (const float*)d_in[7];
    const float* bv   = (const float*)d_in[8];

    float* outp = (float*)d_out;
    const float4* e4 = (const float4*)e;
    float4* eo4 = (float4*)(outp + OUT_ELEMS);

    fused_kernel<<<GRID, 256>>>(x, mask, Wq, bq, Wk, bk, Wv, bv, e4, eo4, outp);
}